// round 11
// baseline (speedup 1.0000x reference)
#include <cuda_runtime.h>
#include <cuda_bf16.h>

#define R_MAX 2.0f
#define DR_MIN 0.02f
#define NBLOCKS 148
#define NTHREADS 800

__device__ unsigned char g_Z8[204800];
__device__ float g_partials[NBLOCKS];
__device__ unsigned int g_count = 0;

__global__ void z_to_u8_kernel(const int* __restrict__ Z, int n)
{
    int i = blockIdx.x * blockDim.x + threadIdx.x;
    int n4 = n >> 2;
    if (i < n4) {
        int4 z = __ldg((const int4*)Z + i);
        ((uchar4*)g_Z8)[i] = make_uchar4((unsigned char)z.x, (unsigned char)z.y,
                                         (unsigned char)z.z, (unsigned char)z.w);
    }
    if (i == 0) {
        for (int k = n4 << 2; k < n; k++) g_Z8[k] = (unsigned char)Z[k];
    }
}

// cos(pi*u) with u^2 = v, Taylor coefficients through v^7 (abs err <= ~4e-6 on [0,1])
#define CC1 -4.934802200544679f
#define CC2  4.058712126416768f
#define CC3 -1.3352627688545895f
#define CC4  0.2353306303588932f
#define CC5 -0.02580689139001406f
#define CC6  0.0019295743094039231f
#define CC7 -0.00010463810492484571f

// 8 replicated tables, stride 129 float2 (1032B => +2 bank shift per copy)
#define TAB_STRIDE 129
#define TAB_BYTES 8256   // 8*129*8

__global__ void __launch_bounds__(NTHREADS, 1)
exp_rep_kernel(const float* __restrict__ dr_vec,
               const int* __restrict__ idx_i,
               const int* __restrict__ idx_j,
               const float* __restrict__ rep_scale,
               const float* __restrict__ rep_prefactor,
               float* __restrict__ out,
               int n_edges, int n_atoms)
{
    extern __shared__ unsigned char smem[];
    float2* s_tab = (float2*)smem;                 // 8 copies
    unsigned char* s_Z = smem + TAB_BYTES;         // n_atoms bytes

    int tid = threadIdx.x;
    int lane = tid & 31;
    if (tid < 119) {
        float2 v = make_float2(fabsf(rep_prefactor[tid]),
                               1.0f / fabsf(rep_scale[tid]));
        #pragma unroll
        for (int cp = 0; cp < 8; cp++)
            s_tab[cp * TAB_STRIDE + tid] = v;
    }
    // stage u8 Z -> smem (16B chunks)
    int n16 = n_atoms >> 4;
    const int4* gZ16 = (const int4*)g_Z8;
    int4* sZ16 = (int4*)s_Z;
    for (int i = tid; i < n16; i += NTHREADS)
        sZ16[i] = __ldg(gZ16 + i);
    for (int i = (n16 << 4) + tid; i < n_atoms; i += NTHREADS)
        s_Z[i] = g_Z8[i];
    __syncthreads();

    const float2* my_tab = s_tab + (lane & 7) * TAB_STRIDE;

    float acc0 = 0.0f, acc1 = 0.0f;
    int m = n_edges >> 2;
    int s = NBLOCKS * NTHREADS;
    const float4* dv4 = (const float4*)dr_vec;
    const int4*   I4  = (const int4*)idx_i;
    const int4*   J4  = (const int4*)idx_j;

    // ---- pipeline: idx prefetched 2 deep, dr_vec 1 deep ----
    int c = blockIdx.x * NTHREADS + tid;
    bool vA = (c < m);
    bool vB = (c + s < m);
    int4 iiA, jjA, iiB, jjB;
    float4 va, vb, vc;
    iiA = jjA = iiB = jjB = make_int4(0, 0, 0, 0);
    va = vb = vc = make_float4(0.f, 0.f, 0.f, 0.f);
    if (vA) {
        iiA = __ldcs(I4 + c);
        jjA = __ldcs(J4 + c);
        va  = __ldcs(dv4 + 3 * c + 0);
        vb  = __ldcs(dv4 + 3 * c + 1);
        vc  = __ldcs(dv4 + 3 * c + 2);
    }
    if (vB) {
        iiB = __ldcs(I4 + c + s);
        jjB = __ldcs(J4 + c + s);
    }

    while (vA) {
        int c1 = c + s;
        int c2 = c + 2 * s;
        bool v1 = vB;
        bool v2 = (c2 < m);

        // prefetch: dr for c1, idx for c2
        float4 nva = va, nvb = vb, nvc = vc;
        int4 nii = iiA, njj = jjA;
        if (v1) {
            nva = __ldcs(dv4 + 3 * c1 + 0);
            nvb = __ldcs(dv4 + 3 * c1 + 1);
            nvc = __ldcs(dv4 + 3 * c1 + 2);
        }
        if (v2) {
            nii = __ldcs(I4 + c2);
            njj = __ldcs(J4 + c2);
        }

        // ---- compute chunk c ----
        float ex[4], ey[4], ez[4];
        ex[0] = va.x; ey[0] = va.y; ez[0] = va.z;
        ex[1] = va.w; ey[1] = vb.x; ez[1] = vb.y;
        ex[2] = vb.z; ey[2] = vb.w; ez[2] = vc.x;
        ex[3] = vc.y; ey[3] = vc.z; ez[3] = vc.w;
        int ii[4] = {iiA.x, iiA.y, iiA.z, iiA.w};
        int jj[4] = {jjA.x, jjA.y, jjA.z, jjA.w};

        int zi[4], zj[4];
        #pragma unroll
        for (int k = 0; k < 4; k++) {
            zi[k] = (int)s_Z[ii[k]];
            zj[k] = (int)s_Z[jj[k]];
        }
        float2 pi[4], pj[4];
        #pragma unroll
        for (int k = 0; k < 4; k++) {
            pi[k] = my_tab[zi[k]];
            pj[k] = my_tab[zj[k]];
        }

        #pragma unroll
        for (int k = 0; k < 4; k++) {
            float r2 = fmaf(ex[k], ex[k], fmaf(ey[k], ey[k], ez[k] * ez[k]));
            float r2c = fmaxf(r2, DR_MIN * DR_MIN);
            float inv_r2 = __fdividef(1.0f, r2c);   // independent of sqrt
            float dr = sqrtf(r2c);
            // cos cutoff via even polynomial in v = r2/4 (no sqrt dependency):
            // 0.5*(1 + cos(pi*dr/2)) ; masked to 0 for dr >= 2 (reference clamp)
            float v = r2c * 0.25f;
            float p = fmaf(v, CC7, CC6);
            p = fmaf(v, p, CC5);
            p = fmaf(v, p, CC4);
            p = fmaf(v, p, CC3);
            p = fmaf(v, p, CC2);
            p = fmaf(v, p, CC1);
            p = fmaf(v, p, 1.0f);
            float cosc = 0.5f * (1.0f + p);
            bool live = (r2c < R_MAX * R_MAX) & (ii[k] != jj[k]);
            float e = __expf(-dr * (pi[k].y + pj[k].y));
            float f = pi[k].x * pj[k].x * e * cosc * inv_r2;
            if (k & 1) acc1 += live ? f : 0.0f;
            else       acc0 += live ? f : 0.0f;
        }

        // rotate pipeline
        c = c1; vA = v1; vB = v2;
        iiA = iiB; jjA = jjB;
        iiB = nii; jjB = njj;
        va = nva; vb = nvb; vc = nvc;
    }

    float acc = acc0 + acc1;

    // remainder edges (n_edges % 4): block 0, thread 0
    if (blockIdx.x == 0 && tid == 0) {
        for (int e = m << 2; e < n_edges; e++) {
            float dx = dr_vec[3*e+0], dy = dr_vec[3*e+1], dz = dr_vec[3*e+2];
            int ii = idx_i[e], jj = idx_j[e];
            float2 pi = my_tab[(int)s_Z[ii]];
            float2 pj = my_tab[(int)s_Z[jj]];
            float r2c = fmaxf(dx*dx + dy*dy + dz*dz, DR_MIN * DR_MIN);
            float dr = sqrtf(r2c);
            float v = r2c * 0.25f;
            float p = fmaf(v, CC7, CC6);
            p = fmaf(v, p, CC5);
            p = fmaf(v, p, CC4);
            p = fmaf(v, p, CC3);
            p = fmaf(v, p, CC2);
            p = fmaf(v, p, CC1);
            p = fmaf(v, p, 1.0f);
            float cosc = 0.5f * (1.0f + p);
            bool live = (r2c < R_MAX * R_MAX) & (ii != jj);
            float f = pi.x * pj.x * __expf(-dr * (pi.y + pj.y)) * cosc *
                      __fdividef(1.0f, r2c);
            acc += live ? f : 0.0f;
        }
    }

    // warp reduce, block reduce, deterministic cross-block finish
    #pragma unroll
    for (int off = 16; off > 0; off >>= 1)
        acc += __shfl_down_sync(0xFFFFFFFF, acc, off);

    __shared__ float s_red[32];
    int warp = tid >> 5;
    if (lane == 0) s_red[warp] = acc;
    __syncthreads();
    if (warp == 0) {
        float v = (tid < (NTHREADS / 32)) ? s_red[tid] : 0.0f;
        #pragma unroll
        for (int off = 16; off > 0; off >>= 1)
            v += __shfl_down_sync(0xFFFFFFFF, v, off);
        if (tid == 0) {
            g_partials[blockIdx.x] = v;
            __threadfence();
            unsigned int ticket = atomicAdd(&g_count, 1u);
            if (ticket == NBLOCKS - 1) {
                float sum = 0.0f;
                #pragma unroll 4
                for (int i = 0; i < NBLOCKS; i++) sum += g_partials[i];
                out[0] = sum;
                g_count = 0;  // reset for next graph replay
            }
        }
    }
}

extern "C" void kernel_launch(void* const* d_in, const int* in_sizes, int n_in,
                              void* d_out, int out_size)
{
    const float* dr_vec        = (const float*)d_in[1];
    const int*   Z             = (const int*)d_in[2];
    const int*   idx           = (const int*)d_in[3];
    const float* rep_scale     = (const float*)d_in[6];
    const float* rep_prefactor = (const float*)d_in[7];
    float* out = (float*)d_out;

    int n_edges = in_sizes[1] / 3;
    int n_atoms = in_sizes[2];
    const int* idx_i = idx;
    const int* idx_j = idx + n_edges;

    int n4 = n_atoms >> 2;
    z_to_u8_kernel<<<(n4 + 255) / 256, 256>>>(Z, n_atoms);

    int smem_bytes = TAB_BYTES + ((n_atoms + 15) & ~15);
    cudaFuncSetAttribute(exp_rep_kernel,
                         cudaFuncAttributeMaxDynamicSharedMemorySize, smem_bytes);

    exp_rep_kernel<<<NBLOCKS, NTHREADS, smem_bytes>>>(
        dr_vec, idx_i, idx_j, rep_scale, rep_prefactor,
        out, n_edges, n_atoms);
}

// round 12
// speedup vs baseline: 1.0627x; 1.0627x over previous
#include <cuda_runtime.h>
#include <cuda_bf16.h>

#define R_MAX 2.0f
#define DR_MIN 0.02f
#define NBLOCKS 148
#define NTHREADS 768

__device__ unsigned char g_Z8[204800];
__device__ float g_partials[NBLOCKS];
__device__ unsigned int g_count = 0;

__global__ void z_to_u8_kernel(const int* __restrict__ Z, int n)
{
    int i = blockIdx.x * blockDim.x + threadIdx.x;
    int n4 = n >> 2;
    if (i < n4) {
        int4 z = __ldg((const int4*)Z + i);
        ((uchar4*)g_Z8)[i] = make_uchar4((unsigned char)z.x, (unsigned char)z.y,
                                         (unsigned char)z.z, (unsigned char)z.w);
    }
    if (i == 0) {
        for (int k = n4 << 2; k < n; k++) g_Z8[k] = (unsigned char)Z[k];
    }
}

// cos(pi*u) with v = u^2, Taylor through v^7 (abs err <= ~4e-6 on v in [0,1])
#define CC1 -4.934802200544679f
#define CC2  4.058712126416768f
#define CC3 -1.3352627688545895f
#define CC4  0.2353306303588932f
#define CC5 -0.02580689139001406f
#define CC6  0.0019295743094039231f
#define CC7 -0.00010463810492484571f

// 8 replicated tables, stride 129 float2 (1032B => +2 bank shift per copy)
#define TAB_STRIDE 129
#define TAB_BYTES 8256   // 8*129*8

__global__ void __launch_bounds__(NTHREADS, 1)
exp_rep_kernel(const float* __restrict__ dr_vec,
               const int* __restrict__ idx_i,
               const int* __restrict__ idx_j,
               const float* __restrict__ rep_scale,
               const float* __restrict__ rep_prefactor,
               float* __restrict__ out,
               int n_edges, int n_atoms)
{
    extern __shared__ unsigned char smem[];
    float2* s_tab = (float2*)smem;                 // 8 copies
    unsigned char* s_Z = smem + TAB_BYTES;         // n_atoms bytes

    int tid = threadIdx.x;
    int lane = tid & 31;
    if (tid < 119) {
        float2 v = make_float2(fabsf(rep_prefactor[tid]),
                               1.0f / fabsf(rep_scale[tid]));
        #pragma unroll
        for (int cp = 0; cp < 8; cp++)
            s_tab[cp * TAB_STRIDE + tid] = v;
    }
    // stage u8 Z -> smem (16B chunks)
    int n16 = n_atoms >> 4;
    const int4* gZ16 = (const int4*)g_Z8;
    int4* sZ16 = (int4*)s_Z;
    for (int i = tid; i < n16; i += NTHREADS)
        sZ16[i] = __ldg(gZ16 + i);
    for (int i = (n16 << 4) + tid; i < n_atoms; i += NTHREADS)
        s_Z[i] = g_Z8[i];
    __syncthreads();

    const float2* my_tab = s_tab + (lane & 7) * TAB_STRIDE;

    float acc0 = 0.0f, acc1 = 0.0f;
    int m = n_edges >> 2;
    int s = NBLOCKS * NTHREADS;
    const float4* dv4 = (const float4*)dr_vec;
    const int4*   I4  = (const int4*)idx_i;
    const int4*   J4  = (const int4*)idx_j;

    // ---- pipeline: idx prefetched 2 deep, dr_vec 1 deep (R10 structure) ----
    int c = blockIdx.x * NTHREADS + tid;
    bool vA = (c < m);
    bool vB = (c + s < m);
    int4 iiA, jjA, iiB, jjB;
    float4 va, vb, vc;
    iiA = jjA = iiB = jjB = make_int4(0, 0, 0, 0);
    va = vb = vc = make_float4(0.f, 0.f, 0.f, 0.f);
    if (vA) {
        iiA = __ldcs(I4 + c);
        jjA = __ldcs(J4 + c);
        va  = __ldcs(dv4 + 3 * c + 0);
        vb  = __ldcs(dv4 + 3 * c + 1);
        vc  = __ldcs(dv4 + 3 * c + 2);
    }
    if (vB) {
        iiB = __ldcs(I4 + c + s);
        jjB = __ldcs(J4 + c + s);
    }

    while (vA) {
        int c1 = c + s;
        int c2 = c + 2 * s;
        bool v1 = vB;
        bool v2 = (c2 < m);

        // prefetch: dr for c1, idx for c2
        float4 nva = va, nvb = vb, nvc = vc;
        int4 nii = iiA, njj = jjA;
        if (v1) {
            nva = __ldcs(dv4 + 3 * c1 + 0);
            nvb = __ldcs(dv4 + 3 * c1 + 1);
            nvc = __ldcs(dv4 + 3 * c1 + 2);
        }
        if (v2) {
            nii = __ldcs(I4 + c2);
            njj = __ldcs(J4 + c2);
        }

        // ---- compute chunk c ----
        float ex[4], ey[4], ez[4];
        ex[0] = va.x; ey[0] = va.y; ez[0] = va.z;
        ex[1] = va.w; ey[1] = vb.x; ez[1] = vb.y;
        ex[2] = vb.z; ey[2] = vb.w; ez[2] = vc.x;
        ex[3] = vc.y; ey[3] = vc.z; ez[3] = vc.w;
        int ii[4] = {iiA.x, iiA.y, iiA.z, iiA.w};
        int jj[4] = {jjA.x, jjA.y, jjA.z, jjA.w};

        int zi[4], zj[4];
        #pragma unroll
        for (int k = 0; k < 4; k++) {
            zi[k] = (int)s_Z[ii[k]];
            zj[k] = (int)s_Z[jj[k]];
        }
        float2 pi[4], pj[4];
        #pragma unroll
        for (int k = 0; k < 4; k++) {
            pi[k] = my_tab[zi[k]];
            pj[k] = my_tab[zj[k]];
        }

        #pragma unroll
        for (int k = 0; k < 4; k++) {
            float r2 = fmaf(ex[k], ex[k], fmaf(ey[k], ey[k], ez[k] * ez[k]));
            float r2c = fmaxf(r2, DR_MIN * DR_MIN);
            float inv_r2 = __fdividef(1.0f, r2c);   // parallel to sqrt chain
            float dr = sqrtf(r2c);
            // cos cutoff: even polynomial in v = r2/4 (no sqrt dependency).
            // reference clamps dr to [0.02, 2]; cos factor is 0 at dr >= 2,
            // so mask instead of clamping high.
            float v = r2c * 0.25f;
            float p = fmaf(v, CC7, CC6);
            p = fmaf(v, p, CC5);
            p = fmaf(v, p, CC4);
            p = fmaf(v, p, CC3);
            p = fmaf(v, p, CC2);
            p = fmaf(v, p, CC1);
            p = fmaf(v, p, 1.0f);
            float cosc = 0.5f * (1.0f + p);
            bool live = (r2c < R_MAX * R_MAX) & (ii[k] != jj[k]);
            float e = __expf(-dr * (pi[k].y + pj[k].y));
            float f = pi[k].x * pj[k].x * e * cosc * inv_r2;
            if (k & 1) acc1 += live ? f : 0.0f;
            else       acc0 += live ? f : 0.0f;
        }

        // rotate pipeline
        c = c1; vA = v1; vB = v2;
        iiA = iiB; jjA = jjB;
        iiB = nii; jjB = njj;
        va = nva; vb = nvb; vc = nvc;
    }

    float acc = acc0 + acc1;

    // remainder edges (n_edges % 4): block 0, thread 0
    if (blockIdx.x == 0 && tid == 0) {
        for (int e = m << 2; e < n_edges; e++) {
            float dx = dr_vec[3*e+0], dy = dr_vec[3*e+1], dz = dr_vec[3*e+2];
            int ii = idx_i[e], jj = idx_j[e];
            float2 pi = my_tab[(int)s_Z[ii]];
            float2 pj = my_tab[(int)s_Z[jj]];
            float r2c = fmaxf(dx*dx + dy*dy + dz*dz, DR_MIN * DR_MIN);
            float dr = sqrtf(r2c);
            float v = r2c * 0.25f;
            float p = fmaf(v, CC7, CC6);
            p = fmaf(v, p, CC5);
            p = fmaf(v, p, CC4);
            p = fmaf(v, p, CC3);
            p = fmaf(v, p, CC2);
            p = fmaf(v, p, CC1);
            p = fmaf(v, p, 1.0f);
            float cosc = 0.5f * (1.0f + p);
            bool live = (r2c < R_MAX * R_MAX) & (ii != jj);
            float f = pi.x * pj.x * __expf(-dr * (pi.y + pj.y)) * cosc *
                      __fdividef(1.0f, r2c);
            acc += live ? f : 0.0f;
        }
    }

    // warp reduce, block reduce, deterministic cross-block finish
    #pragma unroll
    for (int off = 16; off > 0; off >>= 1)
        acc += __shfl_down_sync(0xFFFFFFFF, acc, off);

    __shared__ float s_red[32];
    int warp = tid >> 5;
    if (lane == 0) s_red[warp] = acc;
    __syncthreads();
    if (warp == 0) {
        float v = (tid < (NTHREADS / 32)) ? s_red[tid] : 0.0f;
        #pragma unroll
        for (int off = 16; off > 0; off >>= 1)
            v += __shfl_down_sync(0xFFFFFFFF, v, off);
        if (tid == 0) {
            g_partials[blockIdx.x] = v;
            __threadfence();
            unsigned int ticket = atomicAdd(&g_count, 1u);
            if (ticket == NBLOCKS - 1) {
                float sum = 0.0f;
                #pragma unroll 4
                for (int i = 0; i < NBLOCKS; i++) sum += g_partials[i];
                out[0] = sum;
                g_count = 0;  // reset for next graph replay
            }
        }
    }
}

extern "C" void kernel_launch(void* const* d_in, const int* in_sizes, int n_in,
                              void* d_out, int out_size)
{
    const float* dr_vec        = (const float*)d_in[1];
    const int*   Z             = (const int*)d_in[2];
    const int*   idx           = (const int*)d_in[3];
    const float* rep_scale     = (const float*)d_in[6];
    const float* rep_prefactor = (const float*)d_in[7];
    float* out = (float*)d_out;

    int n_edges = in_sizes[1] / 3;
    int n_atoms = in_sizes[2];
    const int* idx_i = idx;
    const int* idx_j = idx + n_edges;

    int n4 = n_atoms >> 2;
    z_to_u8_kernel<<<(n4 + 255) / 256, 256>>>(Z, n_atoms);

    int smem_bytes = TAB_BYTES + ((n_atoms + 15) & ~15);
    cudaFuncSetAttribute(exp_rep_kernel,
                         cudaFuncAttributeMaxDynamicSharedMemorySize, smem_bytes);

    exp_rep_kernel<<<NBLOCKS, NTHREADS, smem_bytes>>>(
        dr_vec, idx_i, idx_j, rep_scale, rep_prefactor,
        out, n_edges, n_atoms);
}

// round 13
// speedup vs baseline: 1.2518x; 1.1780x over previous
#include <cuda_runtime.h>
#include <cuda_bf16.h>

#define R_MAX 2.0f
#define DR_MIN 0.02f
#define PI_F 3.14159265358979f
#define NBLOCKS 148
#define NTHREADS 768

__device__ unsigned char g_Z8[204800];
__device__ float g_partials[NBLOCKS];
__device__ unsigned int g_count = 0;

__global__ void z_to_u8_kernel(const int* __restrict__ Z, int n)
{
    int i = blockIdx.x * blockDim.x + threadIdx.x;
    int n4 = n >> 2;
    if (i < n4) {
        int4 z = __ldg((const int4*)Z + i);
        ((uchar4*)g_Z8)[i] = make_uchar4((unsigned char)z.x, (unsigned char)z.y,
                                         (unsigned char)z.z, (unsigned char)z.w);
    }
    if (i == 0) {
        for (int k = n4 << 2; k < n; k++) g_Z8[k] = (unsigned char)Z[k];
    }
}

// 8 replicated tables, stride 129 float2 (1032B => +2 bank shift per copy)
#define TAB_STRIDE 129
#define TAB_BYTES 8256   // 8*129*8

__global__ void __launch_bounds__(NTHREADS, 1)
exp_rep_kernel(const float* __restrict__ dr_vec,
               const int* __restrict__ idx_i,
               const int* __restrict__ idx_j,
               const float* __restrict__ rep_scale,
               const float* __restrict__ rep_prefactor,
               float* __restrict__ out,
               int n_edges, int n_atoms)
{
    extern __shared__ unsigned char smem[];
    float2* s_tab = (float2*)smem;                 // 8 copies
    unsigned char* s_Z = smem + TAB_BYTES;         // n_atoms bytes

    int tid = threadIdx.x;
    int lane = tid & 31;
    if (tid < 119) {
        float2 v = make_float2(fabsf(rep_prefactor[tid]),
                               1.0f / fabsf(rep_scale[tid]));
        #pragma unroll
        for (int cp = 0; cp < 8; cp++)
            s_tab[cp * TAB_STRIDE + tid] = v;
    }
    // stage u8 Z -> smem (16B chunks)
    int n16 = n_atoms >> 4;
    const int4* gZ16 = (const int4*)g_Z8;
    int4* sZ16 = (int4*)s_Z;
    for (int i = tid; i < n16; i += NTHREADS)
        sZ16[i] = __ldg(gZ16 + i);
    for (int i = (n16 << 4) + tid; i < n_atoms; i += NTHREADS)
        s_Z[i] = g_Z8[i];
    __syncthreads();

    const float2* my_tab = s_tab + (lane & 7) * TAB_STRIDE;

    float acc0 = 0.0f, acc1 = 0.0f;
    int m = n_edges >> 2;
    int s = NBLOCKS * NTHREADS;
    const float4* dv4 = (const float4*)dr_vec;
    const int4*   I4  = (const int4*)idx_i;
    const int4*   J4  = (const int4*)idx_j;

    // ---- pipeline: idx prefetched 2 deep (regs), dr_vec 1 deep (regs),
    //      plus L2 prefetch hints 3 iterations ahead (no registers) ----
    int c = blockIdx.x * NTHREADS + tid;
    bool vA = (c < m);
    bool vB = (c + s < m);
    int4 iiA, jjA, iiB, jjB;
    float4 va, vb, vc;
    iiA = jjA = iiB = jjB = make_int4(0, 0, 0, 0);
    va = vb = vc = make_float4(0.f, 0.f, 0.f, 0.f);
    if (vA) {
        iiA = __ldcs(I4 + c);
        jjA = __ldcs(J4 + c);
        va  = __ldcs(dv4 + 3 * c + 0);
        vb  = __ldcs(dv4 + 3 * c + 1);
        vc  = __ldcs(dv4 + 3 * c + 2);
    }
    if (vB) {
        iiB = __ldcs(I4 + c + s);
        jjB = __ldcs(J4 + c + s);
    }

    while (vA) {
        int c1 = c + s;
        int c2 = c + 2 * s;
        bool v1 = vB;
        bool v2 = (c2 < m);

        // L2 prefetch hints for 3 iterations ahead (fire-and-forget).
        // Per-lane addresses cover every 128B line of the warp's window.
        int cpre = c + 3 * s;
        if (cpre < m) {
            asm volatile("prefetch.global.L2 [%0];" :: "l"(dv4 + 3 * cpre) : "memory");
            asm volatile("prefetch.global.L2 [%0];" :: "l"(I4 + cpre) : "memory");
            asm volatile("prefetch.global.L2 [%0];" :: "l"(J4 + cpre) : "memory");
        }

        // prefetch: dr for c1, idx for c2
        float4 nva = va, nvb = vb, nvc = vc;
        int4 nii = iiA, njj = jjA;
        if (v1) {
            nva = __ldcs(dv4 + 3 * c1 + 0);
            nvb = __ldcs(dv4 + 3 * c1 + 1);
            nvc = __ldcs(dv4 + 3 * c1 + 2);
        }
        if (v2) {
            nii = __ldcs(I4 + c2);
            njj = __ldcs(J4 + c2);
        }

        // ---- compute chunk c ----
        float ex[4], ey[4], ez[4];
        ex[0] = va.x; ey[0] = va.y; ez[0] = va.z;
        ex[1] = va.w; ey[1] = vb.x; ez[1] = vb.y;
        ex[2] = vb.z; ey[2] = vb.w; ez[2] = vc.x;
        ex[3] = vc.y; ey[3] = vc.z; ez[3] = vc.w;
        int ii[4] = {iiA.x, iiA.y, iiA.z, iiA.w};
        int jj[4] = {jjA.x, jjA.y, jjA.z, jjA.w};

        int zi[4], zj[4];
        #pragma unroll
        for (int k = 0; k < 4; k++) {
            zi[k] = (int)s_Z[ii[k]];
            zj[k] = (int)s_Z[jj[k]];
        }
        float2 pi[4], pj[4];
        #pragma unroll
        for (int k = 0; k < 4; k++) {
            pi[k] = my_tab[zi[k]];
            pj[k] = my_tab[zj[k]];
        }

        #pragma unroll
        for (int k = 0; k < 4; k++) {
            float r2 = fmaf(ex[k], ex[k], fmaf(ey[k], ey[k], ez[k] * ez[k]));
            float r2c = fmaxf(r2, DR_MIN * DR_MIN);
            float inv_r2 = __fdividef(1.0f, r2c);   // parallel to sqrt chain
            float dr = sqrtf(r2c);
            // reference clamps dr to [0.02, 2]; at dr >= 2 the cos factor is
            // exactly 0, so mask instead of clamping high.
            bool live = (dr < R_MAX) & (ii[k] != jj[k]);
            float cosc = 0.5f * (__cosf(dr * (PI_F / R_MAX)) + 1.0f);
            float e = __expf(-dr * (pi[k].y + pj[k].y));
            float f = pi[k].x * pj[k].x * e * cosc * inv_r2;
            if (k & 1) acc1 += live ? f : 0.0f;
            else       acc0 += live ? f : 0.0f;
        }

        // rotate pipeline
        c = c1; vA = v1; vB = v2;
        iiA = iiB; jjA = jjB;
        iiB = nii; jjB = njj;
        va = nva; vb = nvb; vc = nvc;
    }

    float acc = acc0 + acc1;

    // remainder edges (n_edges % 4): block 0, thread 0
    if (blockIdx.x == 0 && tid == 0) {
        for (int e = m << 2; e < n_edges; e++) {
            float dx = dr_vec[3*e+0], dy = dr_vec[3*e+1], dz = dr_vec[3*e+2];
            int ii = idx_i[e], jj = idx_j[e];
            float2 pi = my_tab[(int)s_Z[ii]];
            float2 pj = my_tab[(int)s_Z[jj]];
            float r2c = fmaxf(dx*dx + dy*dy + dz*dz, DR_MIN * DR_MIN);
            float dr = sqrtf(r2c);
            bool live = (dr < R_MAX) & (ii != jj);
            float cosc = 0.5f * (__cosf(dr * (PI_F / R_MAX)) + 1.0f);
            float f = pi.x * pj.x * __expf(-dr * (pi.y + pj.y)) * cosc *
                      __fdividef(1.0f, r2c);
            acc += live ? f : 0.0f;
        }
    }

    // warp reduce, block reduce, deterministic cross-block finish
    #pragma unroll
    for (int off = 16; off > 0; off >>= 1)
        acc += __shfl_down_sync(0xFFFFFFFF, acc, off);

    __shared__ float s_red[32];
    int warp = tid >> 5;
    if (lane == 0) s_red[warp] = acc;
    __syncthreads();
    if (warp == 0) {
        float v = (tid < (NTHREADS / 32)) ? s_red[tid] : 0.0f;
        #pragma unroll
        for (int off = 16; off > 0; off >>= 1)
            v += __shfl_down_sync(0xFFFFFFFF, v, off);
        if (tid == 0) {
            g_partials[blockIdx.x] = v;
            __threadfence();
            unsigned int ticket = atomicAdd(&g_count, 1u);
            if (ticket == NBLOCKS - 1) {
                float sum = 0.0f;
                #pragma unroll 4
                for (int i = 0; i < NBLOCKS; i++) sum += g_partials[i];
                out[0] = sum;
                g_count = 0;  // reset for next graph replay
            }
        }
    }
}

extern "C" void kernel_launch(void* const* d_in, const int* in_sizes, int n_in,
                              void* d_out, int out_size)
{
    const float* dr_vec        = (const float*)d_in[1];
    const int*   Z             = (const int*)d_in[2];
    const int*   idx           = (const int*)d_in[3];
    const float* rep_scale     = (const float*)d_in[6];
    const float* rep_prefactor = (const float*)d_in[7];
    float* out = (float*)d_out;

    int n_edges = in_sizes[1] / 3;
    int n_atoms = in_sizes[2];
    const int* idx_i = idx;
    const int* idx_j = idx + n_edges;

    int n4 = n_atoms >> 2;
    z_to_u8_kernel<<<(n4 + 255) / 256, 256>>>(Z, n_atoms);

    int smem_bytes = TAB_BYTES + ((n_atoms + 15) & ~15);
    cudaFuncSetAttribute(exp_rep_kernel,
                         cudaFuncAttributeMaxDynamicSharedMemorySize, smem_bytes);

    exp_rep_kernel<<<NBLOCKS, NTHREADS, smem_bytes>>>(
        dr_vec, idx_i, idx_j, rep_scale, rep_prefactor,
        out, n_edges, n_atoms);
}